// round 3
// baseline (speedup 1.0000x reference)
#include <cuda_runtime.h>
#include <cuda_bf16.h>

#define N_NODES 100000
#define N_EDGES 1600000
#define D 128

// ---------------- scratch (device globals; no allocation) ----------------
__device__ int   g_deg[N_NODES];      // degree incl. self loop
__device__ int   g_cursor[N_NODES];   // scatter cursors
__device__ int   g_base[N_NODES + 1]; // CSR row offsets (edges only)
__device__ float g_dis[N_NODES];      // deg^{-1/2}
__device__ int   g_src[N_EDGES];      // source node per CSR slot
__device__ float g_h[(size_t)N_NODES * D]; // x @ W^T

// ---------------- packed f32x2 helpers ----------------
__device__ __forceinline__ unsigned long long pk2(float lo, float hi) {
    unsigned long long r;
    asm("mov.b64 %0, {%1, %2};" : "=l"(r) : "f"(lo), "f"(hi));
    return r;
}
__device__ __forceinline__ void unpk2(unsigned long long v, float& lo, float& hi) {
    asm("mov.b64 {%0, %1}, %2;" : "=f"(lo), "=f"(hi) : "l"(v));
}
__device__ __forceinline__ void fma2(unsigned long long& d, unsigned long long a,
                                     unsigned long long b) {
    asm("fma.rn.f32x2 %0, %1, %2, %0;" : "+l"(d) : "l"(a), "l"(b));
}

// ---------------- 1. init ----------------
__global__ void init_kernel() {
    int i = blockIdx.x * blockDim.x + threadIdx.x;
    if (i < N_NODES) {
        g_deg[i] = 1;     // self loop
        g_cursor[i] = 0;
    }
}

// ---------------- 2. degree histogram (edge_index is int32) ----------------
__global__ void hist_kernel(const int* __restrict__ ei) {
    int e = blockIdx.x * blockDim.x + threadIdx.x;
    if (e < N_EDGES) {
        int col = ei[N_EDGES + e];
        if ((unsigned)col < (unsigned)N_NODES)
            atomicAdd(&g_deg[col], 1);
    }
}

// ---------------- 3. single-block scan: base[], dis[] ----------------
__global__ void scan_kernel() {
    __shared__ int s[1024];
    const int t = threadIdx.x;
    const int chunk = (N_NODES + 1023) / 1024;  // 98
    int start = t * chunk;
    int end = start + chunk; if (end > N_NODES) end = N_NODES;
    if (start > N_NODES) start = N_NODES;

    int sum = 0;
    for (int i = start; i < end; i++) sum += g_deg[i] - 1;
    s[t] = sum;
    __syncthreads();
    for (int off = 1; off < 1024; off <<= 1) {
        int v = (t >= off) ? s[t - off] : 0;
        __syncthreads();
        s[t] += v;
        __syncthreads();
    }
    int prefix = (t == 0) ? 0 : s[t - 1];
    for (int i = start; i < end; i++) {
        g_base[i] = prefix;
        int d = g_deg[i];
        prefix += d - 1;
        g_dis[i] = rsqrtf((float)d);
    }
    if (t == 1023) g_base[N_NODES] = s[1023];
}

// ---------------- 4. scatter edges into CSR ----------------
__global__ void scatter_kernel(const int* __restrict__ ei) {
    int e = blockIdx.x * blockDim.x + threadIdx.x;
    if (e < N_EDGES) {
        int row = ei[e];
        int col = ei[N_EDGES + e];
        if ((unsigned)row < (unsigned)N_NODES && (unsigned)col < (unsigned)N_NODES) {
            int pos = g_base[col] + atomicAdd(&g_cursor[col], 1);
            if ((unsigned)pos < (unsigned)N_EDGES)
                g_src[pos] = row;
        }
    }
}

// ---------------- 5. GEMM: h = x @ W^T -------------------------------------
// 64-row x-tile (32KB) + transposed W (64KB) = 96KB smem -> 2 CTAs/SM.
// 256 threads: thread = 4 rows x 8 cols, cols as 4x f32x2 accumulators.
__global__ void gemm_kernel(const float* __restrict__ x, const float* __restrict__ w) {
    extern __shared__ float smem[];
    float* xs = smem;            // [64][128]
    float* wt = smem + 64 * D;   // wt[k][j] = W[j][k]

    const int tid = threadIdx.x;
    const int row0 = blockIdx.x * 64;

    // load x tile (coalesced float4): 64*32 float4
    for (int c = tid; c < 64 * 32; c += 256) {
        int m = c >> 5, k4 = c & 31;
        int row = row0 + m;
        float4 v = make_float4(0.f, 0.f, 0.f, 0.f);
        if (row < N_NODES) v = *(const float4*)&x[(size_t)row * D + k4 * 4];
        *(float4*)&xs[m * D + k4 * 4] = v;
    }
    // load W transposed
    for (int c = tid; c < 128 * 32; c += 256) {
        int j = c & 127, k4 = c >> 7;
        float4 v = *(const float4*)&w[j * D + k4 * 4];
        wt[(k4 * 4 + 0) * D + j] = v.x;
        wt[(k4 * 4 + 1) * D + j] = v.y;
        wt[(k4 * 4 + 2) * D + j] = v.z;
        wt[(k4 * 4 + 3) * D + j] = v.w;
    }
    __syncthreads();

    const int ty = tid >> 4;        // 0..15 -> rows ty*4..+4
    const int tx = tid & 15;        // 0..15 -> cols tx*8..+8
    const int m0 = ty * 4, j0 = tx * 8;

    unsigned long long acc[4][4];
#pragma unroll
    for (int i = 0; i < 4; i++)
#pragma unroll
        for (int j = 0; j < 4; j++) acc[i][j] = 0ull;

#pragma unroll 2
    for (int kk = 0; kk < 128; kk += 4) {
        // a: 4 rows x 4 k-values (vector LDS along k)
        float4 a4[4];
#pragma unroll
        for (int i = 0; i < 4; i++)
            a4[i] = *(const float4*)&xs[(m0 + i) * D + kk];
#pragma unroll
        for (int dk = 0; dk < 4; dk++) {
            int k = kk + dk;
            float4 b0 = *(const float4*)&wt[k * D + j0];
            float4 b1 = *(const float4*)&wt[k * D + j0 + 4];
            unsigned long long bp[4];
            bp[0] = pk2(b0.x, b0.y); bp[1] = pk2(b0.z, b0.w);
            bp[2] = pk2(b1.x, b1.y); bp[3] = pk2(b1.z, b1.w);
#pragma unroll
            for (int i = 0; i < 4; i++) {
                float a = (dk == 0) ? a4[i].x : (dk == 1) ? a4[i].y
                        : (dk == 2) ? a4[i].z : a4[i].w;
                unsigned long long ap = pk2(a, a);
#pragma unroll
                for (int j = 0; j < 4; j++) fma2(acc[i][j], ap, bp[j]);
            }
        }
    }

#pragma unroll
    for (int i = 0; i < 4; i++) {
        int row = row0 + m0 + i;
        if (row < N_NODES) {
            float4 r0, r1;
            unpk2(acc[i][0], r0.x, r0.y); unpk2(acc[i][1], r0.z, r0.w);
            unpk2(acc[i][2], r1.x, r1.y); unpk2(acc[i][3], r1.z, r1.w);
            *(float4*)&g_h[(size_t)row * D + j0] = r0;
            *(float4*)&g_h[(size_t)row * D + j0 + 4] = r1;
        }
    }
}

// ---------------- 6. aggregation: one warp/node, 4x unrolled gathers --------
__global__ void agg_kernel(const float* __restrict__ bias, float* __restrict__ out) {
    int warp = (blockIdx.x * blockDim.x + threadIdx.x) >> 5;
    int lane = threadIdx.x & 31;
    if (warp >= N_NODES) return;
    const int n = warp;

    const float dn = g_dis[n];
    float4 acc = *(const float4*)&g_h[(size_t)n * D + lane * 4];
    float sl = dn * dn;
    acc.x *= sl; acc.y *= sl; acc.z *= sl; acc.w *= sl;

    const int s = g_base[n];
    const int e = g_base[n + 1];
    int idx = s;
    for (; idx + 4 <= e; idx += 4) {
        int r0 = g_src[idx + 0];
        int r1 = g_src[idx + 1];
        int r2 = g_src[idx + 2];
        int r3 = g_src[idx + 3];
        float4 h0 = *(const float4*)&g_h[(size_t)r0 * D + lane * 4];
        float4 h1 = *(const float4*)&g_h[(size_t)r1 * D + lane * 4];
        float4 h2 = *(const float4*)&g_h[(size_t)r2 * D + lane * 4];
        float4 h3 = *(const float4*)&g_h[(size_t)r3 * D + lane * 4];
        float s0 = g_dis[r0] * dn;
        float s1 = g_dis[r1] * dn;
        float s2 = g_dis[r2] * dn;
        float s3 = g_dis[r3] * dn;
        acc.x = fmaf(h0.x, s0, acc.x); acc.y = fmaf(h0.y, s0, acc.y);
        acc.z = fmaf(h0.z, s0, acc.z); acc.w = fmaf(h0.w, s0, acc.w);
        acc.x = fmaf(h1.x, s1, acc.x); acc.y = fmaf(h1.y, s1, acc.y);
        acc.z = fmaf(h1.z, s1, acc.z); acc.w = fmaf(h1.w, s1, acc.w);
        acc.x = fmaf(h2.x, s2, acc.x); acc.y = fmaf(h2.y, s2, acc.y);
        acc.z = fmaf(h2.z, s2, acc.z); acc.w = fmaf(h2.w, s2, acc.w);
        acc.x = fmaf(h3.x, s3, acc.x); acc.y = fmaf(h3.y, s3, acc.y);
        acc.z = fmaf(h3.z, s3, acc.z); acc.w = fmaf(h3.w, s3, acc.w);
    }
    for (; idx < e; idx++) {
        int r = g_src[idx];
        float sc = g_dis[r] * dn;
        float4 hv = *(const float4*)&g_h[(size_t)r * D + lane * 4];
        acc.x = fmaf(hv.x, sc, acc.x);
        acc.y = fmaf(hv.y, sc, acc.y);
        acc.z = fmaf(hv.z, sc, acc.z);
        acc.w = fmaf(hv.w, sc, acc.w);
    }

    float4 bb = *(const float4*)&bias[lane * 4];
    acc.x = fmaxf(acc.x + bb.x, 0.f);
    acc.y = fmaxf(acc.y + bb.y, 0.f);
    acc.z = fmaxf(acc.z + bb.z, 0.f);
    acc.w = fmaxf(acc.w + bb.w, 0.f);
    *(float4*)&out[(size_t)n * D + lane * 4] = acc;
}

// ---------------- launch ----------------
extern "C" void kernel_launch(void* const* d_in, const int* in_sizes, int n_in,
                              void* d_out, int out_size) {
    const float* x    = (const float*)d_in[0];
    const int*   ei   = (const int*)d_in[1];     // int32 (JAX x64 disabled)
    const float* w    = (const float*)d_in[2];
    const float* bias = (const float*)d_in[3];
    float*       out  = (float*)d_out;

    const int gemm_smem = (64 * D + D * D) * (int)sizeof(float);  // 96KB
    cudaFuncSetAttribute(gemm_kernel, cudaFuncAttributeMaxDynamicSharedMemorySize,
                         gemm_smem);

    init_kernel<<<(N_NODES + 255) / 256, 256>>>();
    hist_kernel<<<(N_EDGES + 255) / 256, 256>>>(ei);
    scan_kernel<<<1, 1024>>>();
    scatter_kernel<<<(N_EDGES + 255) / 256, 256>>>(ei);
    gemm_kernel<<<(N_NODES + 63) / 64, 256, gemm_smem>>>(x, w);
    agg_kernel<<<(N_NODES * 32 + 255) / 256, 256>>>(bias, out);
}

// round 4
// speedup vs baseline: 1.0453x; 1.0453x over previous
#include <cuda_runtime.h>
#include <cuda_bf16.h>

#define N_NODES 100000
#define N_EDGES 1600000
#define D 128

// ---------------- scratch (device globals; no allocation) ----------------
__device__ int   g_deg[N_NODES];
__device__ int   g_cursor[N_NODES];
__device__ int   g_base[N_NODES + 1];
__device__ float g_dis[N_NODES];
__device__ int   g_src[N_EDGES];
__device__ float g_h[(size_t)N_NODES * D];

// ---------------- packed f32x2 helpers ----------------
__device__ __forceinline__ unsigned long long pk2(float lo, float hi) {
    unsigned long long r;
    asm("mov.b64 %0, {%1, %2};" : "=l"(r) : "f"(lo), "f"(hi));
    return r;
}
__device__ __forceinline__ void unpk2(unsigned long long v, float& lo, float& hi) {
    asm("mov.b64 {%0, %1}, %2;" : "=f"(lo), "=f"(hi) : "l"(v));
}
__device__ __forceinline__ void fma2(unsigned long long& d, unsigned long long a,
                                     unsigned long long b) {
    asm("fma.rn.f32x2 %0, %1, %2, %0;" : "+l"(d) : "l"(a), "l"(b));
}

// ---------------- 1. init ----------------
__global__ void init_kernel() {
    int i = blockIdx.x * blockDim.x + threadIdx.x;
    if (i < N_NODES) {
        g_deg[i] = 1;     // self loop
        g_cursor[i] = 0;
    }
}

// ---------------- 2. degree histogram: 4 edges/thread via int4 -------------
__global__ void hist_kernel(const int* __restrict__ ei) {
    int t = blockIdx.x * blockDim.x + threadIdx.x;
    int e = t * 4;
    if (e + 4 <= N_EDGES) {
        int4 c = *(const int4*)&ei[N_EDGES + e];
        if ((unsigned)c.x < (unsigned)N_NODES) atomicAdd(&g_deg[c.x], 1);
        if ((unsigned)c.y < (unsigned)N_NODES) atomicAdd(&g_deg[c.y], 1);
        if ((unsigned)c.z < (unsigned)N_NODES) atomicAdd(&g_deg[c.z], 1);
        if ((unsigned)c.w < (unsigned)N_NODES) atomicAdd(&g_deg[c.w], 1);
    } else {
        for (; e < N_EDGES; e++) {
            int col = ei[N_EDGES + e];
            if ((unsigned)col < (unsigned)N_NODES) atomicAdd(&g_deg[col], 1);
        }
    }
}

// ---------------- 3. single-block scan: base[], dis[] ----------------
__global__ void scan_kernel() {
    __shared__ int s[1024];
    const int t = threadIdx.x;
    const int chunk = (N_NODES + 1023) / 1024;  // 98
    int start = t * chunk;
    int end = start + chunk; if (end > N_NODES) end = N_NODES;
    if (start > N_NODES) start = N_NODES;

    int sum = 0;
    for (int i = start; i < end; i++) sum += g_deg[i] - 1;
    s[t] = sum;
    __syncthreads();
    for (int off = 1; off < 1024; off <<= 1) {
        int v = (t >= off) ? s[t - off] : 0;
        __syncthreads();
        s[t] += v;
        __syncthreads();
    }
    int prefix = (t == 0) ? 0 : s[t - 1];
    for (int i = start; i < end; i++) {
        g_base[i] = prefix;
        int d = g_deg[i];
        prefix += d - 1;
        g_dis[i] = rsqrtf((float)d);
    }
    if (t == 1023) g_base[N_NODES] = s[1023];
}

// ---------------- 4. GEMM: h = x @ W^T (R2 128x128x128, f32x2) -------------
// Launched at index 3 so ncu's captured slot profiles THIS kernel.
__global__ void gemm_kernel(const float* __restrict__ x, const float* __restrict__ w) {
    extern __shared__ float smem[];
    float* xs = smem;            // [128][128]
    float* wt = smem + D * D;    // wt[k][j] = W[j][k]

    const int tid = threadIdx.x;
    const int row0 = blockIdx.x * 128;

    for (int c = tid; c < 128 * 32; c += 256) {
        int m = c >> 5, k4 = c & 31;
        int row = row0 + m;
        float4 v = make_float4(0.f, 0.f, 0.f, 0.f);
        if (row < N_NODES) v = *(const float4*)&x[(size_t)row * D + k4 * 4];
        *(float4*)&xs[m * D + k4 * 4] = v;
    }
    for (int c = tid; c < 128 * 32; c += 256) {
        int j = c & 127, k4 = c >> 7;
        float4 v = *(const float4*)&w[j * D + k4 * 4];
        wt[(k4 * 4 + 0) * D + j] = v.x;
        wt[(k4 * 4 + 1) * D + j] = v.y;
        wt[(k4 * 4 + 2) * D + j] = v.z;
        wt[(k4 * 4 + 3) * D + j] = v.w;
    }
    __syncthreads();

    const int ty = tid >> 4;
    const int tx = tid & 15;
    const int m0 = ty * 8, j0 = tx * 8;

    unsigned long long acc[8][4];
#pragma unroll
    for (int i = 0; i < 8; i++)
#pragma unroll
        for (int j = 0; j < 4; j++) acc[i][j] = 0ull;

#pragma unroll 4
    for (int k = 0; k < 128; k++) {
        float a_[8];
#pragma unroll
        for (int i = 0; i < 8; i++) a_[i] = xs[(m0 + i) * D + k];
        float4 b0 = *(const float4*)&wt[k * D + j0];
        float4 b1 = *(const float4*)&wt[k * D + j0 + 4];
        unsigned long long bp[4];
        bp[0] = pk2(b0.x, b0.y); bp[1] = pk2(b0.z, b0.w);
        bp[2] = pk2(b1.x, b1.y); bp[3] = pk2(b1.z, b1.w);
#pragma unroll
        for (int i = 0; i < 8; i++) {
            unsigned long long ap = pk2(a_[i], a_[i]);
#pragma unroll
            for (int j = 0; j < 4; j++) fma2(acc[i][j], ap, bp[j]);
        }
    }

#pragma unroll
    for (int i = 0; i < 8; i++) {
        int row = row0 + m0 + i;
        if (row < N_NODES) {
            float4 r0, r1;
            unpk2(acc[i][0], r0.x, r0.y); unpk2(acc[i][1], r0.z, r0.w);
            unpk2(acc[i][2], r1.x, r1.y); unpk2(acc[i][3], r1.z, r1.w);
            *(float4*)&g_h[(size_t)row * D + j0] = r0;
            *(float4*)&g_h[(size_t)row * D + j0 + 4] = r1;
        }
    }
}

// ---------------- 5. scatter edges into CSR: 4 edges/thread ----------------
__global__ void scatter_kernel(const int* __restrict__ ei) {
    int t = blockIdx.x * blockDim.x + threadIdx.x;
    int e = t * 4;
    if (e + 4 <= N_EDGES) {
        int4 r = *(const int4*)&ei[e];
        int4 c = *(const int4*)&ei[N_EDGES + e];
#pragma unroll
        for (int q = 0; q < 4; q++) {
            int row = (q == 0) ? r.x : (q == 1) ? r.y : (q == 2) ? r.z : r.w;
            int col = (q == 0) ? c.x : (q == 1) ? c.y : (q == 2) ? c.z : c.w;
            if ((unsigned)row < (unsigned)N_NODES && (unsigned)col < (unsigned)N_NODES) {
                int pos = g_base[col] + atomicAdd(&g_cursor[col], 1);
                if ((unsigned)pos < (unsigned)N_EDGES) g_src[pos] = row;
            }
        }
    } else {
        for (; e < N_EDGES; e++) {
            int row = ei[e];
            int col = ei[N_EDGES + e];
            if ((unsigned)row < (unsigned)N_NODES && (unsigned)col < (unsigned)N_NODES) {
                int pos = g_base[col] + atomicAdd(&g_cursor[col], 1);
                if ((unsigned)pos < (unsigned)N_EDGES) g_src[pos] = row;
            }
        }
    }
}

// ---------------- 6. aggregation: warp/node, int4 index loads, MLP>=5 -------
__global__ void agg_kernel(const float* __restrict__ bias, float* __restrict__ out) {
    int warp = (blockIdx.x * blockDim.x + threadIdx.x) >> 5;
    int lane = threadIdx.x & 31;
    if (warp >= N_NODES) return;
    const int n = warp;

    const float dn = g_dis[n];
    float4 acc = *(const float4*)&g_h[(size_t)n * D + lane * 4];
    float sl = dn * dn;
    acc.x *= sl; acc.y *= sl; acc.z *= sl; acc.w *= sl;

    const int s = g_base[n];
    const int e = g_base[n + 1];
    int idx = s;
    int pre = (s + 3) & ~3; if (pre > e) pre = e;
    for (; idx < pre; idx++) {
        int r = g_src[idx];
        float sc = g_dis[r] * dn;
        float4 hv = *(const float4*)&g_h[(size_t)r * D + lane * 4];
        acc.x = fmaf(hv.x, sc, acc.x); acc.y = fmaf(hv.y, sc, acc.y);
        acc.z = fmaf(hv.z, sc, acc.z); acc.w = fmaf(hv.w, sc, acc.w);
    }
    for (; idx + 4 <= e; idx += 4) {
        int4 r4 = *(const int4*)&g_src[idx];      // one uniform LDG.128
        float4 h0 = *(const float4*)&g_h[(size_t)r4.x * D + lane * 4];
        float4 h1 = *(const float4*)&g_h[(size_t)r4.y * D + lane * 4];
        float4 h2 = *(const float4*)&g_h[(size_t)r4.z * D + lane * 4];
        float4 h3 = *(const float4*)&g_h[(size_t)r4.w * D + lane * 4];
        float s0 = g_dis[r4.x] * dn;
        float s1 = g_dis[r4.y] * dn;
        float s2 = g_dis[r4.z] * dn;
        float s3 = g_dis[r4.w] * dn;
        acc.x = fmaf(h0.x, s0, acc.x); acc.y = fmaf(h0.y, s0, acc.y);
        acc.z = fmaf(h0.z, s0, acc.z); acc.w = fmaf(h0.w, s0, acc.w);
        acc.x = fmaf(h1.x, s1, acc.x); acc.y = fmaf(h1.y, s1, acc.y);
        acc.z = fmaf(h1.z, s1, acc.z); acc.w = fmaf(h1.w, s1, acc.w);
        acc.x = fmaf(h2.x, s2, acc.x); acc.y = fmaf(h2.y, s2, acc.y);
        acc.z = fmaf(h2.z, s2, acc.z); acc.w = fmaf(h2.w, s2, acc.w);
        acc.x = fmaf(h3.x, s3, acc.x); acc.y = fmaf(h3.y, s3, acc.y);
        acc.z = fmaf(h3.z, s3, acc.z); acc.w = fmaf(h3.w, s3, acc.w);
    }
    for (; idx < e; idx++) {
        int r = g_src[idx];
        float sc = g_dis[r] * dn;
        float4 hv = *(const float4*)&g_h[(size_t)r * D + lane * 4];
        acc.x = fmaf(hv.x, sc, acc.x); acc.y = fmaf(hv.y, sc, acc.y);
        acc.z = fmaf(hv.z, sc, acc.z); acc.w = fmaf(hv.w, sc, acc.w);
    }

    float4 bb = *(const float4*)&bias[lane * 4];
    acc.x = fmaxf(acc.x + bb.x, 0.f);
    acc.y = fmaxf(acc.y + bb.y, 0.f);
    acc.z = fmaxf(acc.z + bb.z, 0.f);
    acc.w = fmaxf(acc.w + bb.w, 0.f);
    *(float4*)&out[(size_t)n * D + lane * 4] = acc;
}

// ---------------- launch ----------------
extern "C" void kernel_launch(void* const* d_in, const int* in_sizes, int n_in,
                              void* d_out, int out_size) {
    const float* x    = (const float*)d_in[0];
    const int*   ei   = (const int*)d_in[1];     // int32 (JAX x64 disabled)
    const float* w    = (const float*)d_in[2];
    const float* bias = (const float*)d_in[3];
    float*       out  = (float*)d_out;

    const int gemm_smem = 2 * D * D * (int)sizeof(float);  // 128KB
    cudaFuncSetAttribute(gemm_kernel, cudaFuncAttributeMaxDynamicSharedMemorySize,
                         gemm_smem);

    const int e4 = (N_EDGES / 4 + 255) / 256;    // threads cover 4 edges each
    init_kernel<<<(N_NODES + 255) / 256, 256>>>();                     // idx 0
    hist_kernel<<<e4, 256>>>(ei);                                       // idx 1
    scan_kernel<<<1, 1024>>>();                                         // idx 2
    gemm_kernel<<<(N_NODES + 127) / 128, 256, gemm_smem>>>(x, w);       // idx 3 (profiled)
    scatter_kernel<<<e4, 256>>>(ei);                                    // idx 4
    agg_kernel<<<(N_NODES * 32 + 255) / 256, 256>>>(bias, out);         // idx 5
}

// round 6
// speedup vs baseline: 2.1474x; 2.0544x over previous
#include <cuda_runtime.h>
#include <cuda_bf16.h>
#include <cstdint>

#define N_NODES 100000
#define N_EDGES 1600000
#define D 128
#define SCAN_BLOCKS 391   // 391*256 = 100096 >= N_NODES

// ---------------- scratch (device globals; no allocation) ----------------
__device__ int   g_deg[N_NODES];
__device__ int   g_cursor[N_NODES];
__device__ int   g_base[N_NODES + 1];
__device__ float g_dis[N_NODES];
__device__ int   g_src[N_EDGES];
__device__ int   g_bsum[SCAN_BLOCKS];
__device__ float g_h[(size_t)N_NODES * D];

// ---------------- packed f32x2 helpers ----------------
__device__ __forceinline__ unsigned long long pk2(float lo, float hi) {
    unsigned long long r;
    asm("mov.b64 %0, {%1, %2};" : "=l"(r) : "f"(lo), "f"(hi));
    return r;
}
__device__ __forceinline__ void unpk2(unsigned long long v, float& lo, float& hi) {
    asm("mov.b64 {%0, %1}, %2;" : "=f"(lo), "=f"(hi) : "l"(v));
}
__device__ __forceinline__ void fma2(unsigned long long& d, unsigned long long a,
                                     unsigned long long b) {
    asm("fma.rn.f32x2 %0, %1, %2, %0;" : "+l"(d) : "l"(a), "l"(b));
}

// ---------------- 1. init ----------------
__global__ void init_kernel() {
    int i = blockIdx.x * blockDim.x + threadIdx.x;
    if (i < N_NODES) g_deg[i] = 1;   // self loop
}

// ---------------- 2. degree histogram ----------------
__global__ void hist_kernel(const int* __restrict__ ei) {
    int e = blockIdx.x * blockDim.x + threadIdx.x;
    if (e < N_EDGES) {
        int col = ei[N_EDGES + e];
        if ((unsigned)col < (unsigned)N_NODES)
            atomicAdd(&g_deg[col], 1);
    }
}

// ---------------- 3a. per-block sums of (deg-1) ----------------
__global__ void scanA_kernel() {
    __shared__ int s[256];
    int t = threadIdx.x, i = blockIdx.x * 256 + t;
    int v = (i < N_NODES) ? g_deg[i] - 1 : 0;
    s[t] = v; __syncthreads();
    for (int o = 128; o > 0; o >>= 1) {
        if (t < o) s[t] += s[t + o];
        __syncthreads();
    }
    if (t == 0) g_bsum[blockIdx.x] = s[0];
}

// ---------------- 3b. scan block sums (exclusive) ----------------
__global__ void scanB_kernel() {
    __shared__ int s[512];
    int t = threadIdx.x;
    int v = (t < SCAN_BLOCKS) ? g_bsum[t] : 0;
    s[t] = v; __syncthreads();
    for (int o = 1; o < 512; o <<= 1) {
        int u = (t >= o) ? s[t - o] : 0;
        __syncthreads();
        s[t] += u;
        __syncthreads();
    }
    if (t < SCAN_BLOCKS) g_bsum[t] = s[t] - v;  // exclusive prefix of block sums
}

// ---------------- 3c. finalize base[], dis[], cursor ----------------
__global__ void scanC_kernel() {
    __shared__ int s[256];
    int t = threadIdx.x, i = blockIdx.x * 256 + t;
    int d = (i < N_NODES) ? g_deg[i] : 1;
    int v = (i < N_NODES) ? d - 1 : 0;
    s[t] = v; __syncthreads();
    for (int o = 1; o < 256; o <<= 1) {
        int u = (t >= o) ? s[t - o] : 0;
        __syncthreads();
        s[t] += u;
        __syncthreads();
    }
    int excl = s[t] - v + g_bsum[blockIdx.x];
    if (i < N_NODES) {
        g_base[i] = excl;
        g_cursor[i] = 0;
        g_dis[i] = rsqrtf((float)d);
    }
    if (i == N_NODES - 1) g_base[N_NODES] = excl + v;
}

// ---------------- 4. GEMM: h = x @ W^T ----------------
// smem: W transposed only (64KB) -> 2 CTAs/SM (16 warps). x-tile (64KB) is
// served from L1 via LDG.128 broadcast (quad shared by 16 tx-threads).
// 256 threads: 8 rows x 8 cols each; k-loop in steps of 4 with vector loads.
__global__ void __launch_bounds__(256, 2)
gemm_kernel(const float* __restrict__ x, const float* __restrict__ w) {
    extern __shared__ float wt[];   // wt[k][j] = W[j][k], 128x128

    const int tid = threadIdx.x;
    const int row0 = blockIdx.x * 128;

    // load W transposed (coalesced float4 in, scattered scalar out)
    for (int c = tid; c < 128 * 32; c += 256) {
        int j = c & 127, k4 = c >> 7;
        float4 v = *(const float4*)&w[j * D + k4 * 4];
        wt[(k4 * 4 + 0) * D + j] = v.x;
        wt[(k4 * 4 + 1) * D + j] = v.y;
        wt[(k4 * 4 + 2) * D + j] = v.z;
        wt[(k4 * 4 + 3) * D + j] = v.w;
    }
    __syncthreads();

    const int ty = tid >> 4;        // 0..15 -> rows ty*8..+8
    const int tx = tid & 15;        // 0..15 -> cols tx*8..+8
    const int m0 = ty * 8, j0 = tx * 8;

    // clamp row indices for safe loads; stores are guarded exactly
    const float* xr[8];
#pragma unroll
    for (int i = 0; i < 8; i++) {
        int row = row0 + m0 + i;
        if (row > N_NODES - 1) row = N_NODES - 1;
        xr[i] = x + (size_t)row * D;
    }

    unsigned long long acc[8][4];
#pragma unroll
    for (int i = 0; i < 8; i++)
#pragma unroll
        for (int j = 0; j < 4; j++) acc[i][j] = 0ull;

    for (int kk = 0; kk < 128; kk += 4) {
        float4 a4[8];
#pragma unroll
        for (int i = 0; i < 8; i++)
            a4[i] = *(const float4*)(xr[i] + kk);   // LDG.128, L1 broadcast
#pragma unroll
        for (int dk = 0; dk < 4; dk++) {
            int k = kk + dk;
            float4 b0 = *(const float4*)&wt[k * D + j0];
            float4 b1 = *(const float4*)&wt[k * D + j0 + 4];
            unsigned long long bp[4];
            bp[0] = pk2(b0.x, b0.y); bp[1] = pk2(b0.z, b0.w);
            bp[2] = pk2(b1.x, b1.y); bp[3] = pk2(b1.z, b1.w);
#pragma unroll
            for (int i = 0; i < 8; i++) {
                float a = (dk == 0) ? a4[i].x : (dk == 1) ? a4[i].y
                        : (dk == 2) ? a4[i].z : a4[i].w;
                unsigned long long ap = pk2(a, a);
#pragma unroll
                for (int j = 0; j < 4; j++) fma2(acc[i][j], ap, bp[j]);
            }
        }
    }

#pragma unroll
    for (int i = 0; i < 8; i++) {
        int row = row0 + m0 + i;
        if (row < N_NODES) {
            float4 r0, r1;
            unpk2(acc[i][0], r0.x, r0.y); unpk2(acc[i][1], r0.z, r0.w);
            unpk2(acc[i][2], r1.x, r1.y); unpk2(acc[i][3], r1.z, r1.w);
            *(float4*)&g_h[(size_t)row * D + j0] = r0;
            *(float4*)&g_h[(size_t)row * D + j0 + 4] = r1;
        }
    }
}

// ---------------- 5. scatter edges into CSR ----------------
__global__ void scatter_kernel(const int* __restrict__ ei) {
    int e = blockIdx.x * blockDim.x + threadIdx.x;
    if (e < N_EDGES) {
        int row = ei[e];
        int col = ei[N_EDGES + e];
        if ((unsigned)row < (unsigned)N_NODES && (unsigned)col < (unsigned)N_NODES) {
            int pos = g_base[col] + atomicAdd(&g_cursor[col], 1);
            if ((unsigned)pos < (unsigned)N_EDGES)
                g_src[pos] = row;
        }
    }
}

// ---------------- 6. aggregation: one warp per node (R2 form) ----------------
__global__ void agg_kernel(const float* __restrict__ bias, float* __restrict__ out) {
    int warp = (blockIdx.x * blockDim.x + threadIdx.x) >> 5;
    int lane = threadIdx.x & 31;
    if (warp >= N_NODES) return;
    const int n = warp;

    const float dn = g_dis[n];
    float4 acc = *(const float4*)&g_h[(size_t)n * D + lane * 4];
    float sl = dn * dn;
    acc.x *= sl; acc.y *= sl; acc.z *= sl; acc.w *= sl;

    const int s = g_base[n];
    const int e = g_base[n + 1];
    for (int idx = s; idx < e; idx++) {
        int r = g_src[idx];
        float sc = g_dis[r] * dn;
        float4 hv = *(const float4*)&g_h[(size_t)r * D + lane * 4];
        acc.x = fmaf(hv.x, sc, acc.x);
        acc.y = fmaf(hv.y, sc, acc.y);
        acc.z = fmaf(hv.z, sc, acc.z);
        acc.w = fmaf(hv.w, sc, acc.w);
    }

    float4 bb = *(const float4*)&bias[lane * 4];
    acc.x = fmaxf(acc.x + bb.x, 0.f);
    acc.y = fmaxf(acc.y + bb.y, 0.f);
    acc.z = fmaxf(acc.z + bb.z, 0.f);
    acc.w = fmaxf(acc.w + bb.w, 0.f);
    *(float4*)&out[(size_t)n * D + lane * 4] = acc;
}

// ---------------- launch ----------------
extern "C" void kernel_launch(void* const* d_in, const int* in_sizes, int n_in,
                              void* d_out, int out_size) {
    const float* x    = (const float*)d_in[0];
    const int*   ei   = (const int*)d_in[1];     // int32 (JAX x64 disabled)
    const float* w    = (const float*)d_in[2];
    const float* bias = (const float*)d_in[3];
    float*       out  = (float*)d_out;

    const int gemm_smem = D * D * (int)sizeof(float);   // 64KB (W only)
    cudaFuncSetAttribute(gemm_kernel, cudaFuncAttributeMaxDynamicSharedMemorySize,
                         gemm_smem);

    init_kernel<<<(N_NODES + 255) / 256, 256>>>();                      // idx 0
    hist_kernel<<<(N_EDGES + 255) / 256, 256>>>(ei);                    // idx 1
    scanA_kernel<<<SCAN_BLOCKS, 256>>>();                               // idx 2
    gemm_kernel<<<(N_NODES + 127) / 128, 256, gemm_smem>>>(x, w);       // idx 3 (profiled)
    scanB_kernel<<<1, 512>>>();                                         // idx 4
    scanC_kernel<<<SCAN_BLOCKS, 256>>>();                               // idx 5
    scatter_kernel<<<(N_EDGES + 255) / 256, 256>>>(ei);                 // idx 6
    agg_kernel<<<(N_NODES * 32 + 255) / 256, 256>>>(bias, out);         // idx 7
}